// round 4
// baseline (speedup 1.0000x reference)
#include <cuda_runtime.h>
#include <cooperative_groups.h>

namespace cg = cooperative_groups;

#define NSEQ 384
#define IND  350
#define G4   1024
#define ZSP  68
#define BSP  260

// ---------------- scratch (device globals) -----------------------------------
__device__ float g_xT[IND * NSEQ];          // x transposed [350][384]
__device__ float g_gx[2][NSEQ][G4];         // gate preactivations (incl. biases)
__device__ float g_HT[512 * NSEQ];          // h transposed [512][384]
__device__ float g_AB[NSEQ * 512];          // [384][A(256) | B(256)]
__device__ float g_W2T[256 * 256];          // W2 transposed [k][n]

// ---------------- 1) embedding gather -> xT ----------------------------------
__global__ __launch_bounds__(352) void embed_kernel(
    const int* __restrict__ wid, const int* __restrict__ tyid,
    const float* __restrict__ etab, const float* __restrict__ ttab)
{
    int t = blockIdx.x, d = threadIdx.x;
    if (d < IND) {
        float v = (d < 300) ? etab[wid[t] * 300 + d]
                            : ttab[tyid[t] * 50 + (d - 300)];
        g_xT[d * NSEQ + t] = v;
    }
}

// ---------------- 2) gx = x @ Wih^T + bih + bhh (both dirs) -------------------
__global__ __launch_bounds__(384) void gx_kernel(
    const float* __restrict__ Wih_f, const float* __restrict__ bih_f, const float* __restrict__ bhh_f,
    const float* __restrict__ Wih_b, const float* __restrict__ bih_b, const float* __restrict__ bhh_b)
{
    int dir = blockIdx.y;
    const float* Wih = dir ? Wih_b : Wih_f;
    const float* bi  = dir ? bih_b : bih_f;
    const float* bh  = dir ? bhh_b : bhh_f;
    int t = threadIdx.x;
    int G0 = blockIdx.x * 8;
    const float* wp[8];
#pragma unroll
    for (int g = 0; g < 8; g++) wp[g] = Wih + (G0 + g) * IND;
    float acc[8] = {0.f,0.f,0.f,0.f,0.f,0.f,0.f,0.f};
    for (int k = 0; k < IND; k++) {
        float xv = g_xT[k * NSEQ + t];
#pragma unroll
        for (int g = 0; g < 8; g++) acc[g] = fmaf(xv, wp[g][k], acc[g]);
    }
#pragma unroll
    for (int g = 0; g < 8; g++)
        g_gx[dir][t][G0 + g] = acc[g] + bi[G0 + g] + bh[G0 + g];
}

// ---------------- 3) W2 transpose --------------------------------------------
__global__ __launch_bounds__(256) void w2t_kernel(const float* __restrict__ W2)
{
    int k = blockIdx.x, n = threadIdx.x;
    g_W2T[k * 256 + n] = W2[n * 256 + k];
}

// ---------------- fast activations -------------------------------------------
__device__ __forceinline__ float fast_sigmoid(float x) {
    return 1.f / (1.f + __expf(-x));
}
__device__ __forceinline__ float fast_tanh(float x) {
    return 1.f - 2.f / (__expf(2.f * x) + 1.f);
}

// ---------------- cluster smem / mbarrier helpers -----------------------------
__device__ __forceinline__ unsigned smem_u32(const void* p) {
    return (unsigned)__cvta_generic_to_shared(p);
}
__device__ __forceinline__ unsigned mapa_u32(unsigned local_addr, unsigned rank) {
    unsigned r;
    asm("mapa.shared::cluster.u32 %0, %1, %2;" : "=r"(r) : "r"(local_addr), "r"(rank));
    return r;
}
__device__ __forceinline__ void st_cluster_f32(unsigned addr, float v) {
    asm volatile("st.shared::cluster.f32 [%0], %1;" :: "r"(addr), "f"(v) : "memory");
}
__device__ __forceinline__ void bar_arrive_remote(unsigned cluster_addr) {
    asm volatile("mbarrier.arrive.release.cluster.shared::cluster.b64 _, [%0];"
                 :: "r"(cluster_addr) : "memory");
}
__device__ __forceinline__ void bar_wait(unsigned local_addr, unsigned parity) {
    unsigned done;
    asm volatile(
        "{\n\t.reg .pred p;\n\t"
        "mbarrier.try_wait.parity.acquire.cluster.shared::cta.b64 p, [%1], %2;\n\t"
        "selp.b32 %0, 1, 0, p;\n\t}"
        : "=r"(done) : "r"(local_addr), "r"(parity) : "memory");
    while (!done) {
        asm volatile(
            "{\n\t.reg .pred p;\n\t"
            "mbarrier.try_wait.parity.acquire.cluster.shared::cta.b64 p, [%1], %2;\n\t"
            "selp.b32 %0, 1, 0, p;\n\t}"
            : "=r"(done) : "r"(local_addr), "r"(parity) : "memory");
    }
}

// ---------------- 4) BiLSTM: 2 clusters x 8 CTAs, Whh in registers -----------
// Double-buffered h in DSMEM; sync via per-buffer mbarriers (count = 256 =
// 8 CTAs x 32 writer lanes, each lane release-arrives on every peer).
__global__ void __cluster_dims__(8, 1, 1) __launch_bounds__(256, 1)
lstm_kernel(const float* __restrict__ Whh_f, const float* __restrict__ Whh_b)
{
    __shared__ __align__(16) float hb[2][256];
    __shared__ __align__(16) float psum[2][256];
    __shared__ __align__(16) unsigned long long bar[2];   // contiguous: bar1 = bar0 + 8B

    cg::cluster_group cluster = cg::this_cluster();
    int rk  = (int)cluster.block_rank();
    int dir = blockIdx.x >> 3;
    const float* Whh = dir ? Whh_b : Whh_f;
    int tid  = threadIdx.x;
    int l    = tid & 127;
    int half = tid >> 7;
    int G    = ((l >> 5) << 8) + (rk << 5) + (l & 31);

    float w[128];
    const float* wsrc = Whh + G * 256 + half * 128;
#pragma unroll
    for (int q = 0; q < 128; q += 4) {
        float4 v = *(const float4*)&wsrc[q];
        w[q] = v.x; w[q + 1] = v.y; w[q + 2] = v.z; w[q + 3] = v.w;
    }
    hb[0][tid] = 0.f;
    if (tid == 0) {
        asm volatile("mbarrier.init.shared.b64 [%0], %1;"
                     :: "r"(smem_u32(&bar[0])), "r"(256u) : "memory");
        asm volatile("mbarrier.init.shared.b64 [%0], %1;"
                     :: "r"(smem_u32(&bar[1])), "r"(256u) : "memory");
    }
    float c = 0.f;

    unsigned hrem[8], brem[8];          // 32-bit cluster-shared addresses
    if (tid < 32) {
        unsigned h0 = smem_u32(&hb[0][0]);
        unsigned b0 = smem_u32(&bar[0]);
#pragma unroll
        for (int pr = 0; pr < 8; pr++) {
            hrem[pr] = mapa_u32(h0, pr);
            brem[pr] = mapa_u32(b0, pr);
        }
    }
    __syncthreads();
    cluster.sync();   // barriers + hb[0] visible cluster-wide before first step

    const float* gx = &g_gx[dir][0][0];
    unsigned bloc0 = smem_u32(&bar[0]);
    unsigned ph[2] = {0u, 0u};

    for (int t = 0; t < NSEQ; t++) {
        int cur = t & 1, nxt = cur ^ 1;
        int idx = dir ? (NSEQ - 1 - t) : t;

        float gxv0 = 0.f, gxv1 = 0.f, gxv2 = 0.f, gxv3 = 0.f;
        if (tid < 32) {  // prefetch gate preactivations before the barrier wait
            const float* gp = gx + idx * G4 + (rk << 5) + tid;
            gxv0 = gp[0]; gxv1 = gp[256]; gxv2 = gp[512]; gxv3 = gp[768];
        }

        if (t > 0) { bar_wait(bloc0 + (unsigned)(cur * 8), ph[cur]); ph[cur] ^= 1; }

        const float* h = &hb[cur][half * 128];
        float a0 = 0.f, a1 = 0.f, a2 = 0.f, a3 = 0.f;
#pragma unroll
        for (int q = 0; q < 128; q += 4) {
            float4 hv = *(const float4*)&h[q];
            a0 = fmaf(w[q],     hv.x, a0);
            a1 = fmaf(w[q + 1], hv.y, a1);
            a2 = fmaf(w[q + 2], hv.z, a2);
            a3 = fmaf(w[q + 3], hv.w, a3);
        }
        psum[cur][tid] = (a0 + a1) + (a2 + a3);
        __syncthreads();

        if (tid < 32) {
            const float* pc = &psum[cur][0];
            float ai = pc[tid]       + pc[128 + tid] + gxv0;
            float af = pc[32 + tid]  + pc[160 + tid] + gxv1;
            float ag = pc[64 + tid]  + pc[192 + tid] + gxv2;
            float ao = pc[96 + tid]  + pc[224 + tid] + gxv3;
            float iv = fast_sigmoid(ai);
            float fv = fast_sigmoid(af);
            float gv = fast_tanh(ag);
            float ov = fast_sigmoid(ao);
            c = fv * c + iv * gv;
            float hn = ov * fast_tanh(c);
            int col = (rk << 5) + tid;
            if (t < NSEQ - 1) {
                unsigned off4 = (unsigned)(((nxt << 8) + col) << 2);
                unsigned boff = (unsigned)(nxt * 8);
#pragma unroll
                for (int pr = 0; pr < 8; pr++) st_cluster_f32(hrem[pr] + off4, hn);
#pragma unroll
                for (int pr = 0; pr < 8; pr++) bar_arrive_remote(brem[pr] + boff);
            }
            g_HT[(dir * 256 + col) * NSEQ + idx] = hn;
        }
    }
    cluster.sync();   // no CTA exits while peers may still touch its smem
}

// ---------------- 5) A|B = h @ [W1a|W1b]^T ------------------------------------
__global__ __launch_bounds__(384) void ab_kernel(const float* __restrict__ W1)
{
    int t = threadIdx.x;
    int f0 = blockIdx.x * 8;
    const float* wp[8];
#pragma unroll
    for (int g = 0; g < 8; g++) {
        int f = f0 + g;
        wp[g] = (f < 256) ? (W1 + f * 1024) : (W1 + (f - 256) * 1024 + 512);
    }
    float acc[8] = {0.f,0.f,0.f,0.f,0.f,0.f,0.f,0.f};
    for (int k = 0; k < 512; k++) {
        float hv = g_HT[k * NSEQ + t];
#pragma unroll
        for (int g = 0; g < 8; g++) acc[g] = fmaf(hv, wp[g][k], acc[g]);
    }
#pragma unroll
    for (int g = 0; g < 8; g++) g_AB[t * 512 + f0 + g] = acc[g];
}

// ---------------- 6) fused pair MLP ------------------------------------------
#define SM_W2 (64 * BSP)            // 16640
#define SM_Z  (SM_W2 + 16 * 256)    // 20736
#define SM_A  (SM_Z + 16 * ZSP)     // 21824
#define SM_TOT (SM_A + 256)         // 22080 floats = 88320 B

__global__ __launch_bounds__(256, 2) void pair_kernel(
    const float* __restrict__ b1, const float* __restrict__ b2,
    const float* __restrict__ Wf, const float* __restrict__ bf,
    float* __restrict__ out)
{
    extern __shared__ float sm[];
    float* Bsm  = sm;               // [64][BSP]  (reused as y later)
    float* w2sm = sm + SM_W2;       // [16][256]  (reused as WfT later)
    float* zsm  = sm + SM_Z;        // [16][ZSP]
    float* Asm  = sm + SM_A;        // [256] A_i + b1

    int tid = threadIdx.x;
    int i  = blockIdx.y;
    int j0 = blockIdx.x * 64;

#pragma unroll
    for (int it = 0; it < 16; it++) {
        int lin = tid + it * 256;
        int p = lin >> 6, k4 = (lin & 63) << 2;
        float4 v = *(const float4*)&g_AB[(j0 + p) * 512 + 256 + k4];
        *(float4*)&Bsm[p * BSP + k4] = v;
    }
    Asm[tid] = g_AB[i * 512 + tid] + b1[tid];

    int ps = tid & 15, ns = tid >> 4;
    unsigned long long acc2[32];
#pragma unroll
    for (int q = 0; q < 32; q++) acc2[q] = 0ull;
    int zkk = tid & 15, zp0 = (tid >> 4) << 2;

    for (int kc = 0; kc < 16; kc++) {
        int K0 = kc << 4;
        __syncthreads();
#pragma unroll
        for (int it = 0; it < 4; it++) {
            int kk = (tid >> 6) + (it << 2);
            int n4 = (tid & 63) << 2;
            *(float4*)&w2sm[kk * 256 + n4] = *(const float4*)&g_W2T[(K0 + kk) * 256 + n4];
        }
        {
            float a_ = Asm[K0 + zkk];
            float4 zv;
            float v0 = a_ + Bsm[(zp0 + 0) * BSP + K0 + zkk]; zv.x = fmaxf(v0, 0.01f * v0);
            float v1 = a_ + Bsm[(zp0 + 1) * BSP + K0 + zkk]; zv.y = fmaxf(v1, 0.01f * v1);
            float v2 = a_ + Bsm[(zp0 + 2) * BSP + K0 + zkk]; zv.z = fmaxf(v2, 0.01f * v2);
            float v3 = a_ + Bsm[(zp0 + 3) * BSP + K0 + zkk]; zv.w = fmaxf(v3, 0.01f * v3);
            *(float4*)&zsm[zkk * ZSP + zp0] = zv;
        }
        __syncthreads();
#pragma unroll
        for (int kk = 0; kk < 16; kk++) {
            float4 z4 = *(const float4*)&zsm[kk * ZSP + (ps << 2)];
            const float* wr = &w2sm[kk * 256 + (ns << 4)];
            unsigned long long wv2[8];
#pragma unroll
            for (int u = 0; u < 4; u++) {
                ulonglong2 t2 = *(const ulonglong2*)&wr[u * 4];
                wv2[u * 2] = t2.x; wv2[u * 2 + 1] = t2.y;
            }
            float zz[4] = {z4.x, z4.y, z4.z, z4.w};
#pragma unroll
            for (int q = 0; q < 4; q++) {
                unsigned long long zq;
                asm("mov.b64 %0, {%1, %1};" : "=l"(zq) : "f"(zz[q]));
#pragma unroll
                for (int j2 = 0; j2 < 8; j2++)
                    asm("fma.rn.f32x2 %0, %1, %2, %0;"
                        : "+l"(acc2[q * 8 + j2]) : "l"(zq), "l"(wv2[j2]));
            }
        }
    }
    __syncthreads();
    {
        float* ysm = Bsm;
        float2 b2v[8];
#pragma unroll
        for (int j2 = 0; j2 < 8; j2++)
            b2v[j2] = *(const float2*)&b2[(ns << 4) + j2 * 2];
#pragma unroll
        for (int q = 0; q < 4; q++) {
            int p = (ps << 2) + q;
#pragma unroll
            for (int j2 = 0; j2 < 8; j2++) {
                float lo, hi;
                asm("mov.b64 {%0, %1}, %2;" : "=f"(lo), "=f"(hi) : "l"(acc2[q * 8 + j2]));
                lo += b2v[j2].x; hi += b2v[j2].y;
                float2 yv;
                yv.x = fmaxf(lo, 0.01f * lo);
                yv.y = fmaxf(hi, 0.01f * hi);
                *(float2*)&ysm[p * BSP + (ns << 4) + j2 * 2] = yv;
            }
        }
        float* wfT = w2sm;                      // [256][16] transposed Wf
#pragma unroll
        for (int it = 0; it < 16; it++) {
            int idx = tid + it * 256;
            int r = idx >> 8, n = idx & 255;
            wfT[n * 16 + r] = Wf[r * 256 + n];
        }
        __syncthreads();
#pragma unroll
        for (int it = 0; it < 4; it++) {
            int oidx = tid + it * 256;
            int p = oidx >> 4, r = oidx & 15;
            float acc = bf[r];
            for (int n = 0; n < 256; n += 4) {
                float4 y4 = *(const float4*)&ysm[p * BSP + n];
                acc = fmaf(y4.x, wfT[(n + 0) * 16 + r], acc);
                acc = fmaf(y4.y, wfT[(n + 1) * 16 + r], acc);
                acc = fmaf(y4.z, wfT[(n + 2) * 16 + r], acc);
                acc = fmaf(y4.w, wfT[(n + 3) * 16 + r], acc);
            }
            out[(i * NSEQ + j0 + p) * 16 + r] = acc;
        }
    }
}

// ---------------- launch ------------------------------------------------------
extern "C" void kernel_launch(void* const* d_in, const int* in_sizes, int n_in,
                              void* d_out, int out_size) {
    const int*   wid   = (const int*)d_in[0];
    const int*   tyid  = (const int*)d_in[1];
    const float* etab  = (const float*)d_in[2];
    const float* ttab  = (const float*)d_in[3];
    const float* Wih_f = (const float*)d_in[4];
    const float* Whh_f = (const float*)d_in[5];
    const float* bih_f = (const float*)d_in[6];
    const float* bhh_f = (const float*)d_in[7];
    const float* Wih_b = (const float*)d_in[8];
    const float* Whh_b = (const float*)d_in[9];
    const float* bih_b = (const float*)d_in[10];
    const float* bhh_b = (const float*)d_in[11];
    const float* W1    = (const float*)d_in[12];
    const float* b1    = (const float*)d_in[13];
    const float* W2    = (const float*)d_in[14];
    const float* b2    = (const float*)d_in[15];
    const float* Wf    = (const float*)d_in[16];
    const float* bf    = (const float*)d_in[17];
    float* out = (float*)d_out;

    cudaFuncSetAttribute(pair_kernel,
                         cudaFuncAttributeMaxDynamicSharedMemorySize, 90112);

    embed_kernel<<<NSEQ, 352>>>(wid, tyid, etab, ttab);
    gx_kernel<<<dim3(128, 2), 384>>>(Wih_f, bih_f, bhh_f, Wih_b, bih_b, bhh_b);
    w2t_kernel<<<256, 256>>>(W2);
    lstm_kernel<<<16, 256>>>(Whh_f, Whh_b);
    ab_kernel<<<64, 384>>>(W1);
    pair_kernel<<<dim3(6, NSEQ), 256, SM_TOT * 4>>>(b1, b2, Wf, bf, out);
}

// round 7
// speedup vs baseline: 1.4468x; 1.4468x over previous
#include <cuda_runtime.h>
#include <cooperative_groups.h>

namespace cg = cooperative_groups;

#define NSEQ 384
#define IND  350
#define G4   1024
#define ZSP  68
#define BSP  260

// ---------------- scratch (device globals) -----------------------------------
__device__ float g_xT[IND * NSEQ];          // x transposed [350][384]
__device__ float g_gx[2][NSEQ][G4];         // gate preactivations (incl. biases)
__device__ float g_HT[512 * NSEQ];          // h transposed [512][384]
__device__ float g_AB[NSEQ * 512];          // [384][A(256) | B(256)]
__device__ float g_W2T[256 * 256];          // W2 transposed [k][n]

// ---------------- 1) embedding gather -> xT ----------------------------------
__global__ __launch_bounds__(352) void embed_kernel(
    const int* __restrict__ wid, const int* __restrict__ tyid,
    const float* __restrict__ etab, const float* __restrict__ ttab)
{
    int t = blockIdx.x, d = threadIdx.x;
    if (d < IND) {
        float v = (d < 300) ? etab[wid[t] * 300 + d]
                            : ttab[tyid[t] * 50 + (d - 300)];
        g_xT[d * NSEQ + t] = v;
    }
}

// ---------------- 2) gx = x @ Wih^T + bih + bhh (both dirs) -------------------
__global__ __launch_bounds__(384) void gx_kernel(
    const float* __restrict__ Wih_f, const float* __restrict__ bih_f, const float* __restrict__ bhh_f,
    const float* __restrict__ Wih_b, const float* __restrict__ bih_b, const float* __restrict__ bhh_b)
{
    int dir = blockIdx.y;
    const float* Wih = dir ? Wih_b : Wih_f;
    const float* bi  = dir ? bih_b : bih_f;
    const float* bh  = dir ? bhh_b : bhh_f;
    int t = threadIdx.x;
    int G0 = blockIdx.x * 8;
    const float* wp[8];
#pragma unroll
    for (int g = 0; g < 8; g++) wp[g] = Wih + (G0 + g) * IND;
    float acc[8] = {0.f,0.f,0.f,0.f,0.f,0.f,0.f,0.f};
    for (int k = 0; k < IND; k++) {
        float xv = g_xT[k * NSEQ + t];
#pragma unroll
        for (int g = 0; g < 8; g++) acc[g] = fmaf(xv, wp[g][k], acc[g]);
    }
#pragma unroll
    for (int g = 0; g < 8; g++)
        g_gx[dir][t][G0 + g] = acc[g] + bi[G0 + g] + bh[G0 + g];
}

// ---------------- 3) W2 transpose --------------------------------------------
__global__ __launch_bounds__(256) void w2t_kernel(const float* __restrict__ W2)
{
    int k = blockIdx.x, n = threadIdx.x;
    g_W2T[k * 256 + n] = W2[n * 256 + k];
}

// ---------------- fast activations -------------------------------------------
__device__ __forceinline__ float fast_sigmoid(float x) {
    return 1.f / (1.f + __expf(-x));
}
__device__ __forceinline__ float fast_tanh(float x) {
    return 1.f - 2.f / (__expf(2.f * x) + 1.f);
}

// ---------------- 4) BiLSTM: 2 clusters x 8 CTAs, Whh in registers -----------
// PROVEN sync skeleton (R2): cg cluster.sync per step + generic DSMEM stores
// via map_shared_rank. Compute-side improvements only:
//   - gx prefetched into registers BEFORE the sync point (off the L2 chain)
//   - packed f32x2 recurrent dot (64 FFMA2 instead of 128 FFMA)
//   - single psum buffer, ONE __syncthreads per step, fused 8-way reduce
//   - MUFU-based sigmoid/tanh in the serial warp-0 segment
__global__ void __cluster_dims__(8, 1, 1) __launch_bounds__(256, 1)
lstm_kernel(const float* __restrict__ Whh_f, const float* __restrict__ Whh_b)
{
    __shared__ __align__(16) float hb[2][256];
    __shared__ __align__(16) float psum[256];

    cg::cluster_group cluster = cg::this_cluster();
    int rk  = (int)cluster.block_rank();
    int dir = blockIdx.x >> 3;
    const float* Whh = dir ? Whh_b : Whh_f;
    int tid  = threadIdx.x;
    int l    = tid & 127;
    int half = tid >> 7;
    int G    = ((l >> 5) << 8) + (rk << 5) + (l & 31);

    // Whh row slice packed as f32x2 pairs in registers (64 x u64 = 128 regs)
    unsigned long long w2r[64];
    const float* wsrc = Whh + G * 256 + half * 128;
#pragma unroll
    for (int q = 0; q < 32; q++) {
        float4 v = *(const float4*)&wsrc[q * 4];
        asm("mov.b64 %0, {%1, %2};" : "=l"(w2r[2 * q])     : "f"(v.x), "f"(v.y));
        asm("mov.b64 %0, {%1, %2};" : "=l"(w2r[2 * q + 1]) : "f"(v.z), "f"(v.w));
    }
    hb[0][tid] = 0.f;
    float c = 0.f;

    float* dsth[8];                  // generic peer pointers (as in passing R2)
    if (tid < 32) {
#pragma unroll
        for (int pr = 0; pr < 8; pr++)
            dsth[pr] = cluster.map_shared_rank(&hb[0][0], pr);
    }
    __syncthreads();
    cluster.sync();                  // hb[0] zeroed + visible cluster-wide

    const float* gx = &g_gx[dir][0][0];

    for (int t = 0; t < NSEQ; t++) {
        int cur = t & 1, nxt = cur ^ 1;
        int idx = dir ? (NSEQ - 1 - t) : t;

        float gxv0 = 0.f, gxv1 = 0.f, gxv2 = 0.f, gxv3 = 0.f;
        if (tid < 32) {  // prefetch: in flight across the dot + syncthreads
            const float* gp = gx + idx * G4 + (rk << 5) + tid;
            gxv0 = gp[0]; gxv1 = gp[256]; gxv2 = gp[512]; gxv3 = gp[768];
        }

        // packed f32x2 dot over h(t-1): 64 FFMA2
        const ulonglong2* h2 = (const ulonglong2*)&hb[cur][half * 128];
        unsigned long long a0 = 0ull, a1 = 0ull, a2 = 0ull, a3 = 0ull;
#pragma unroll
        for (int q = 0; q < 32; q += 2) {
            ulonglong2 hv0 = h2[q];
            ulonglong2 hv1 = h2[q + 1];
            asm("fma.rn.f32x2 %0, %1, %2, %0;" : "+l"(a0) : "l"(w2r[2*q]),   "l"(hv0.x));
            asm("fma.rn.f32x2 %0, %1, %2, %0;" : "+l"(a1) : "l"(w2r[2*q+1]), "l"(hv0.y));
            asm("fma.rn.f32x2 %0, %1, %2, %0;" : "+l"(a2) : "l"(w2r[2*q+2]), "l"(hv1.x));
            asm("fma.rn.f32x2 %0, %1, %2, %0;" : "+l"(a3) : "l"(w2r[2*q+3]), "l"(hv1.y));
        }
        float s0, s1, s2, s3, s4, s5, s6, s7;
        asm("mov.b64 {%0, %1}, %2;" : "=f"(s0), "=f"(s1) : "l"(a0));
        asm("mov.b64 {%0, %1}, %2;" : "=f"(s2), "=f"(s3) : "l"(a1));
        asm("mov.b64 {%0, %1}, %2;" : "=f"(s4), "=f"(s5) : "l"(a2));
        asm("mov.b64 {%0, %1}, %2;" : "=f"(s6), "=f"(s7) : "l"(a3));
        psum[tid] = ((s0 + s1) + (s2 + s3)) + ((s4 + s5) + (s6 + s7));
        __syncthreads();

        if (tid < 32) {
            float ai = psum[tid]       + psum[128 + tid] + gxv0;
            float af = psum[32 + tid]  + psum[160 + tid] + gxv1;
            float ag = psum[64 + tid]  + psum[192 + tid] + gxv2;
            float ao = psum[96 + tid]  + psum[224 + tid] + gxv3;
            float iv = fast_sigmoid(ai);
            float fv = fast_sigmoid(af);
            float gv = fast_tanh(ag);
            float ov = fast_sigmoid(ao);
            c = fv * c + iv * gv;
            float hn = ov * fast_tanh(c);
            int col = (rk << 5) + tid;
            if (t < NSEQ - 1) {
                int off = (nxt << 8) + col;
#pragma unroll
                for (int pr = 0; pr < 8; pr++) dsth[pr][off] = hn;
            }
            g_HT[(dir * 256 + col) * NSEQ + idx] = hn;
        }
        cluster.sync();   // release writer stores; ends the step (as in R2)
    }
}

// ---------------- 5) A|B = h @ [W1a|W1b]^T ------------------------------------
__global__ __launch_bounds__(384) void ab_kernel(const float* __restrict__ W1)
{
    int t = threadIdx.x;
    int f0 = blockIdx.x * 8;
    const float* wp[8];
#pragma unroll
    for (int g = 0; g < 8; g++) {
        int f = f0 + g;
        wp[g] = (f < 256) ? (W1 + f * 1024) : (W1 + (f - 256) * 1024 + 512);
    }
    float acc[8] = {0.f,0.f,0.f,0.f,0.f,0.f,0.f,0.f};
    for (int k = 0; k < 512; k++) {
        float hv = g_HT[k * NSEQ + t];
#pragma unroll
        for (int g = 0; g < 8; g++) acc[g] = fmaf(hv, wp[g][k], acc[g]);
    }
#pragma unroll
    for (int g = 0; g < 8; g++) g_AB[t * 512 + f0 + g] = acc[g];
}

// ---------------- 6) fused pair MLP ------------------------------------------
#define SM_W2 (64 * BSP)            // 16640
#define SM_Z  (SM_W2 + 16 * 256)    // 20736
#define SM_A  (SM_Z + 16 * ZSP)     // 21824
#define SM_TOT (SM_A + 256)         // 22080 floats = 88320 B

__global__ __launch_bounds__(256, 2) void pair_kernel(
    const float* __restrict__ b1, const float* __restrict__ b2,
    const float* __restrict__ Wf, const float* __restrict__ bf,
    float* __restrict__ out)
{
    extern __shared__ float sm[];
    float* Bsm  = sm;               // [64][BSP]  (reused as y later)
    float* w2sm = sm + SM_W2;       // [16][256]  (reused as WfT later)
    float* zsm  = sm + SM_Z;        // [16][ZSP]
    float* Asm  = sm + SM_A;        // [256] A_i + b1

    int tid = threadIdx.x;
    int i  = blockIdx.y;
    int j0 = blockIdx.x * 64;

#pragma unroll
    for (int it = 0; it < 16; it++) {
        int lin = tid + it * 256;
        int p = lin >> 6, k4 = (lin & 63) << 2;
        float4 v = *(const float4*)&g_AB[(j0 + p) * 512 + 256 + k4];
        *(float4*)&Bsm[p * BSP + k4] = v;
    }
    Asm[tid] = g_AB[i * 512 + tid] + b1[tid];

    int ps = tid & 15, ns = tid >> 4;
    unsigned long long acc2[32];
#pragma unroll
    for (int q = 0; q < 32; q++) acc2[q] = 0ull;
    int zkk = tid & 15, zp0 = (tid >> 4) << 2;

    for (int kc = 0; kc < 16; kc++) {
        int K0 = kc << 4;
        __syncthreads();
#pragma unroll
        for (int it = 0; it < 4; it++) {
            int kk = (tid >> 6) + (it << 2);
            int n4 = (tid & 63) << 2;
            *(float4*)&w2sm[kk * 256 + n4] = *(const float4*)&g_W2T[(K0 + kk) * 256 + n4];
        }
        {
            float a_ = Asm[K0 + zkk];
            float4 zv;
            float v0 = a_ + Bsm[(zp0 + 0) * BSP + K0 + zkk]; zv.x = fmaxf(v0, 0.01f * v0);
            float v1 = a_ + Bsm[(zp0 + 1) * BSP + K0 + zkk]; zv.y = fmaxf(v1, 0.01f * v1);
            float v2 = a_ + Bsm[(zp0 + 2) * BSP + K0 + zkk]; zv.z = fmaxf(v2, 0.01f * v2);
            float v3 = a_ + Bsm[(zp0 + 3) * BSP + K0 + zkk]; zv.w = fmaxf(v3, 0.01f * v3);
            *(float4*)&zsm[zkk * ZSP + zp0] = zv;
        }
        __syncthreads();
#pragma unroll
        for (int kk = 0; kk < 16; kk++) {
            float4 z4 = *(const float4*)&zsm[kk * ZSP + (ps << 2)];
            const float* wr = &w2sm[kk * 256 + (ns << 4)];
            unsigned long long wv2[8];
#pragma unroll
            for (int u = 0; u < 4; u++) {
                ulonglong2 t2 = *(const ulonglong2*)&wr[u * 4];
                wv2[u * 2] = t2.x; wv2[u * 2 + 1] = t2.y;
            }
            float zz[4] = {z4.x, z4.y, z4.z, z4.w};
#pragma unroll
            for (int q = 0; q < 4; q++) {
                unsigned long long zq;
                asm("mov.b64 %0, {%1, %1};" : "=l"(zq) : "f"(zz[q]));
#pragma unroll
                for (int j2 = 0; j2 < 8; j2++)
                    asm("fma.rn.f32x2 %0, %1, %2, %0;"
                        : "+l"(acc2[q * 8 + j2]) : "l"(zq), "l"(wv2[j2]));
            }
        }
    }
    __syncthreads();
    {
        float* ysm = Bsm;
        float2 b2v[8];
#pragma unroll
        for (int j2 = 0; j2 < 8; j2++)
            b2v[j2] = *(const float2*)&b2[(ns << 4) + j2 * 2];
#pragma unroll
        for (int q = 0; q < 4; q++) {
            int p = (ps << 2) + q;
#pragma unroll
            for (int j2 = 0; j2 < 8; j2++) {
                float lo, hi;
                asm("mov.b64 {%0, %1}, %2;" : "=f"(lo), "=f"(hi) : "l"(acc2[q * 8 + j2]));
                lo += b2v[j2].x; hi += b2v[j2].y;
                float2 yv;
                yv.x = fmaxf(lo, 0.01f * lo);
                yv.y = fmaxf(hi, 0.01f * hi);
                *(float2*)&ysm[p * BSP + (ns << 4) + j2 * 2] = yv;
            }
        }
        float* wfT = w2sm;                      // [256][16] transposed Wf
#pragma unroll
        for (int it = 0; it < 16; it++) {
            int idx = tid + it * 256;
            int r = idx >> 8, n = idx & 255;
            wfT[n * 16 + r] = Wf[r * 256 + n];
        }
        __syncthreads();
#pragma unroll
        for (int it = 0; it < 4; it++) {
            int oidx = tid + it * 256;
            int p = oidx >> 4, r = oidx & 15;
            float acc = bf[r];
            for (int n = 0; n < 256; n += 4) {
                float4 y4 = *(const float4*)&ysm[p * BSP + n];
                acc = fmaf(y4.x, wfT[(n + 0) * 16 + r], acc);
                acc = fmaf(y4.y, wfT[(n + 1) * 16 + r], acc);
                acc = fmaf(y4.z, wfT[(n + 2) * 16 + r], acc);
                acc = fmaf(y4.w, wfT[(n + 3) * 16 + r], acc);
            }
            out[(i * NSEQ + j0 + p) * 16 + r] = acc;
        }
    }
}

// ---------------- launch ------------------------------------------------------
extern "C" void kernel_launch(void* const* d_in, const int* in_sizes, int n_in,
                              void* d_out, int out_size) {
    const int*   wid   = (const int*)d_in[0];
    const int*   tyid  = (const int*)d_in[1];
    const float* etab  = (const float*)d_in[2];
    const float* ttab  = (const float*)d_in[3];
    const float* Wih_f = (const float*)d_in[4];
    const float* Whh_f = (const float*)d_in[5];
    const float* bih_f = (const float*)d_in[6];
    const float* bhh_f = (const float*)d_in[7];
    const float* Wih_b = (const float*)d_in[8];
    const float* Whh_b = (const float*)d_in[9];
    const float* bih_b = (const float*)d_in[10];
    const float* bhh_b = (const float*)d_in[11];
    const float* W1    = (const float*)d_in[12];
    const float* b1    = (const float*)d_in[13];
    const float* W2    = (const float*)d_in[14];
    const float* b2    = (const float*)d_in[15];
    const float* Wf    = (const float*)d_in[16];
    const float* bf    = (const float*)d_in[17];
    float* out = (float*)d_out;

    cudaFuncSetAttribute(pair_kernel,
                         cudaFuncAttributeMaxDynamicSharedMemorySize, 90112);

    embed_kernel<<<NSEQ, 352>>>(wid, tyid, etab, ttab);
    gx_kernel<<<dim3(128, 2), 384>>>(Wih_f, bih_f, bhh_f, Wih_b, bih_b, bhh_b);
    w2t_kernel<<<256, 256>>>(W2);
    lstm_kernel<<<16, 256>>>(Whh_f, Whh_b);
    ab_kernel<<<64, 384>>>(W1);
    pair_kernel<<<dim3(6, NSEQ), 256, SM_TOT * 4>>>(b1, b2, Wf, bf, out);
}

// round 11
// speedup vs baseline: 1.9125x; 1.3219x over previous
#include <cuda_runtime.h>
#include <cooperative_groups.h>

namespace cg = cooperative_groups;

#define NSEQ 384
#define IND  350
#define G4   1024

// ---------------- scratch (device globals) -----------------------------------
__device__ float g_xT[IND * NSEQ];          // x transposed [350][384]
__device__ float g_gx[2][NSEQ][G4];         // gate preactivations (incl. biases)
__device__ float g_HT[512 * NSEQ];          // h transposed [512][384]
__device__ float g_AB[NSEQ * 512];          // [384][A(256) | B(256)]

// ---------------- 1) embedding gather -> xT ----------------------------------
__global__ __launch_bounds__(352) void embed_kernel(
    const int* __restrict__ wid, const int* __restrict__ tyid,
    const float* __restrict__ etab, const float* __restrict__ ttab)
{
    int t = blockIdx.x, d = threadIdx.x;
    if (d < IND) {
        float v = (d < 300) ? etab[wid[t] * 300 + d]
                            : ttab[tyid[t] * 50 + (d - 300)];
        g_xT[d * NSEQ + t] = v;
    }
}

// ---------------- 2) gx = x @ Wih^T + bih + bhh (both dirs) -------------------
__global__ __launch_bounds__(384) void gx_kernel(
    const float* __restrict__ Wih_f, const float* __restrict__ bih_f, const float* __restrict__ bhh_f,
    const float* __restrict__ Wih_b, const float* __restrict__ bih_b, const float* __restrict__ bhh_b)
{
    int dir = blockIdx.y;
    const float* Wih = dir ? Wih_b : Wih_f;
    const float* bi  = dir ? bih_b : bih_f;
    const float* bh  = dir ? bhh_b : bhh_f;
    int t = threadIdx.x;
    int G0 = blockIdx.x * 8;
    const float* wp[8];
#pragma unroll
    for (int g = 0; g < 8; g++) wp[g] = Wih + (G0 + g) * IND;
    float acc[8] = {0.f,0.f,0.f,0.f,0.f,0.f,0.f,0.f};
    for (int k = 0; k < IND; k++) {
        float xv = g_xT[k * NSEQ + t];
#pragma unroll
        for (int g = 0; g < 8; g++) acc[g] = fmaf(xv, wp[g][k], acc[g]);
    }
#pragma unroll
    for (int g = 0; g < 8; g++)
        g_gx[dir][t][G0 + g] = acc[g] + bi[G0 + g] + bh[G0 + g];
}

// ---------------- fast activations -------------------------------------------
__device__ __forceinline__ float fast_sigmoid(float x) {
    return 1.f / (1.f + __expf(-x));
}
__device__ __forceinline__ float fast_tanh(float x) {
    return 1.f - 2.f / (__expf(2.f * x) + 1.f);
}

// ---------------- 4) BiLSTM (IDENTICAL to passing R7) -------------------------
__global__ void __cluster_dims__(8, 1, 1) __launch_bounds__(256, 1)
lstm_kernel(const float* __restrict__ Whh_f, const float* __restrict__ Whh_b)
{
    __shared__ __align__(16) float hb[2][256];
    __shared__ __align__(16) float psum[256];

    cg::cluster_group cluster = cg::this_cluster();
    int rk  = (int)cluster.block_rank();
    int dir = blockIdx.x >> 3;
    const float* Whh = dir ? Whh_b : Whh_f;
    int tid  = threadIdx.x;
    int l    = tid & 127;
    int half = tid >> 7;
    int G    = ((l >> 5) << 8) + (rk << 5) + (l & 31);

    unsigned long long w2r[64];
    const float* wsrc = Whh + G * 256 + half * 128;
#pragma unroll
    for (int q = 0; q < 32; q++) {
        float4 v = *(const float4*)&wsrc[q * 4];
        asm("mov.b64 %0, {%1, %2};" : "=l"(w2r[2 * q])     : "f"(v.x), "f"(v.y));
        asm("mov.b64 %0, {%1, %2};" : "=l"(w2r[2 * q + 1]) : "f"(v.z), "f"(v.w));
    }
    hb[0][tid] = 0.f;
    float c = 0.f;

    float* dsth[8];
    if (tid < 32) {
#pragma unroll
        for (int pr = 0; pr < 8; pr++)
            dsth[pr] = cluster.map_shared_rank(&hb[0][0], pr);
    }
    __syncthreads();
    cluster.sync();

    const float* gx = &g_gx[dir][0][0];

    for (int t = 0; t < NSEQ; t++) {
        int cur = t & 1, nxt = cur ^ 1;
        int idx = dir ? (NSEQ - 1 - t) : t;

        float gxv0 = 0.f, gxv1 = 0.f, gxv2 = 0.f, gxv3 = 0.f;
        if (tid < 32) {
            const float* gp = gx + idx * G4 + (rk << 5) + tid;
            gxv0 = gp[0]; gxv1 = gp[256]; gxv2 = gp[512]; gxv3 = gp[768];
        }

        const ulonglong2* h2 = (const ulonglong2*)&hb[cur][half * 128];
        unsigned long long a0 = 0ull, a1 = 0ull, a2 = 0ull, a3 = 0ull;
#pragma unroll
        for (int q = 0; q < 32; q += 2) {
            ulonglong2 hv0 = h2[q];
            ulonglong2 hv1 = h2[q + 1];
            asm("fma.rn.f32x2 %0, %1, %2, %0;" : "+l"(a0) : "l"(w2r[2*q]),   "l"(hv0.x));
            asm("fma.rn.f32x2 %0, %1, %2, %0;" : "+l"(a1) : "l"(w2r[2*q+1]), "l"(hv0.y));
            asm("fma.rn.f32x2 %0, %1, %2, %0;" : "+l"(a2) : "l"(w2r[2*q+2]), "l"(hv1.x));
            asm("fma.rn.f32x2 %0, %1, %2, %0;" : "+l"(a3) : "l"(w2r[2*q+3]), "l"(hv1.y));
        }
        float s0, s1, s2, s3, s4, s5, s6, s7;
        asm("mov.b64 {%0, %1}, %2;" : "=f"(s0), "=f"(s1) : "l"(a0));
        asm("mov.b64 {%0, %1}, %2;" : "=f"(s2), "=f"(s3) : "l"(a1));
        asm("mov.b64 {%0, %1}, %2;" : "=f"(s4), "=f"(s5) : "l"(a2));
        asm("mov.b64 {%0, %1}, %2;" : "=f"(s6), "=f"(s7) : "l"(a3));
        psum[tid] = ((s0 + s1) + (s2 + s3)) + ((s4 + s5) + (s6 + s7));
        __syncthreads();

        if (tid < 32) {
            float ai = psum[tid]       + psum[128 + tid] + gxv0;
            float af = psum[32 + tid]  + psum[160 + tid] + gxv1;
            float ag = psum[64 + tid]  + psum[192 + tid] + gxv2;
            float ao = psum[96 + tid]  + psum[224 + tid] + gxv3;
            float iv = fast_sigmoid(ai);
            float fv = fast_sigmoid(af);
            float gv = fast_tanh(ag);
            float ov = fast_sigmoid(ao);
            c = fv * c + iv * gv;
            float hn = ov * fast_tanh(c);
            int col = (rk << 5) + tid;
            if (t < NSEQ - 1) {
                int off = (nxt << 8) + col;
#pragma unroll
                for (int pr = 0; pr < 8; pr++) dsth[pr][off] = hn;
            }
            g_HT[(dir * 256 + col) * NSEQ + idx] = hn;
        }
        cluster.sync();
    }
}

// ---------------- 5) A|B = h @ [W1a|W1b]^T ------------------------------------
__global__ __launch_bounds__(384) void ab_kernel(const float* __restrict__ W1)
{
    int t = threadIdx.x;
    int f0 = blockIdx.x * 8;
    const float* wp[8];
#pragma unroll
    for (int g = 0; g < 8; g++) {
        int f = f0 + g;
        wp[g] = (f < 256) ? (W1 + f * 1024) : (W1 + (f - 256) * 1024 + 512);
    }
    float acc[8] = {0.f,0.f,0.f,0.f,0.f,0.f,0.f,0.f};
    for (int k = 0; k < 512; k++) {
        float hv = g_HT[k * NSEQ + t];
#pragma unroll
        for (int g = 0; g < 8; g++) acc[g] = fmaf(hv, wp[g][k], acc[g]);
    }
#pragma unroll
    for (int g = 0; g < 8; g++) g_AB[t * 512 + f0 + g] = acc[g];
}

// ---------------- 6) pair MLP via mma.sync tf32 (sm_80+ HMMA path) ------------
// Per CTA: 2 i x 64 j = M=128 pairs, N=256, K=256. Each warp: 16 M-rows x 256 N.
// W2 streamed in 8 chunks of 32 rows (smem total ~186KB, well under the cap).
// smem floats, stride 260 (bank-conflict-free fragment loads):
#define ZST   260
#define OF_Z  0                         // Z / Y  [128][260]
#define OF_W2 (128 * ZST)               // W2 chunk [32][260]
#define OF_WF (OF_W2 + 32 * ZST)        // Wf [16][260]
#define OF_A  (OF_WF + 16 * ZST)        // A_i + b1 [2][256]
#define OF_B2 (OF_A + 512)              // b2 [256]
#define P3_TOT ((OF_B2 + 256) * 4)      // 186112 bytes

__device__ __forceinline__ unsigned f2tf(float f) {
    unsigned r;
    asm("cvt.rna.tf32.f32 %0, %1;" : "=r"(r) : "f"(f));
    return r;
}
__device__ __forceinline__ float lky(float v) { return fmaxf(v, 0.01f * v); }

#define MMA_TF32(d, a0, a1, a2, a3, b0, b1)                                     \
    asm volatile("mma.sync.aligned.m16n8k8.row.col.f32.tf32.tf32.f32 "          \
                 "{%0,%1,%2,%3}, {%4,%5,%6,%7}, {%8,%9}, {%0,%1,%2,%3};"        \
                 : "+f"((d)[0]), "+f"((d)[1]), "+f"((d)[2]), "+f"((d)[3])       \
                 : "r"(a0), "r"(a1), "r"(a2), "r"(a3), "r"(b0), "r"(b1))

__global__ __launch_bounds__(256, 1) void pair3_kernel(
    const float* __restrict__ b1, const float* __restrict__ b2,
    const float* __restrict__ W2, const float* __restrict__ Wf,
    const float* __restrict__ bf, float* __restrict__ out)
{
    extern __shared__ __align__(16) float sm[];
    int tid = threadIdx.x, wid = tid >> 5, lane = tid & 31;
    int i0 = blockIdx.y * 2, j0 = blockIdx.x * 64;
    int lq = lane >> 2, lr = lane & 3;        // quad row / col within frag

    // stage A rows (+b1), b2, Wf
    sm[OF_A + tid]       = g_AB[(i0 + 0) * 512 + tid] + b1[tid];
    sm[OF_A + 256 + tid] = g_AB[(i0 + 1) * 512 + tid] + b1[tid];
    sm[OF_B2 + tid] = b2[tid];
#pragma unroll
    for (int it = 0; it < 16; it++) {
        int idx = tid + it * 256;             // 4096 = 16 rows x 256 k
        int r = idx >> 8, k = idx & 255;
        sm[OF_WF + r * ZST + k] = __uint_as_float(f2tf(Wf[r * 256 + k]));
    }
    __syncthreads();

    // build Z = tf32(leaky(A_ii + B_jj + b1))  [128][256]
#pragma unroll
    for (int it = 0; it < 32; it++) {
        int lin = tid + it * 256;             // 8192 float4
        int p = lin >> 6, k4 = (lin & 63) << 2;
        int ii = p >> 6, jj = p & 63;
        float4 bv = *(const float4*)&g_AB[(j0 + jj) * 512 + 256 + k4];
        const float4 av = *(const float4*)&sm[OF_A + ii * 256 + k4];
        float4 z;
        z.x = __uint_as_float(f2tf(lky(av.x + bv.x)));
        z.y = __uint_as_float(f2tf(lky(av.y + bv.y)));
        z.z = __uint_as_float(f2tf(lky(av.z + bv.z)));
        z.w = __uint_as_float(f2tf(lky(av.w + bv.w)));
        *(float4*)&sm[OF_Z + p * ZST + k4] = z;
    }

    int mrow = wid * 16;
    float acc[128];                            // [ntile 32][4]
#pragma unroll
    for (int q = 0; q < 128; q++) acc[q] = 0.f;

    const unsigned* zp0 = (const unsigned*)&sm[OF_Z + (mrow + lq) * ZST + lr];
    const unsigned* zp1 = (const unsigned*)&sm[OF_Z + (mrow + 8 + lq) * ZST + lr];

#pragma unroll
    for (int nc = 0; nc < 8; nc++) {
        // load W2 chunk rows [nc*32, nc*32+32), tf32
#pragma unroll
        for (int it = 0; it < 8; it++) {
            int lin = tid + it * 256;          // 2048 float4
            int row = lin >> 6, k4 = (lin & 63) << 2;
            float4 v = *(const float4*)&W2[(nc * 32 + row) * 256 + k4];
            float4 w;
            w.x = __uint_as_float(f2tf(v.x)); w.y = __uint_as_float(f2tf(v.y));
            w.z = __uint_as_float(f2tf(v.z)); w.w = __uint_as_float(f2tf(v.w));
            *(float4*)&sm[OF_W2 + row * ZST + k4] = w;
        }
        __syncthreads();

        const unsigned* wp = (const unsigned*)&sm[OF_W2 + lq * ZST + lr];
        for (int k0 = 0; k0 < 256; k0 += 8) {
            unsigned a0 = zp0[k0], a1 = zp1[k0], a2 = zp0[k0 + 4], a3 = zp1[k0 + 4];
#pragma unroll
            for (int nt = 0; nt < 4; nt++) {
                unsigned bb0 = wp[nt * 8 * ZST + k0];
                unsigned bb1 = wp[nt * 8 * ZST + k0 + 4];
                MMA_TF32(&acc[(nc * 4 + nt) * 4], a0, a1, a2, a3, bb0, bb1);
            }
        }
        __syncthreads();
    }

    // epilogue: Y = tf32(leaky(D + b2)) over Z buffer
#pragma unroll
    for (int nt = 0; nt < 32; nt++) {
        int n0 = nt * 8 + 2 * lr;
        float bb0 = sm[OF_B2 + n0], bb1 = sm[OF_B2 + n0 + 1];
        sm[OF_Z + (mrow + lq) * ZST + n0]         = __uint_as_float(f2tf(lky(acc[nt*4+0] + bb0)));
        sm[OF_Z + (mrow + lq) * ZST + n0 + 1]     = __uint_as_float(f2tf(lky(acc[nt*4+1] + bb1)));
        sm[OF_Z + (mrow + 8 + lq) * ZST + n0]     = __uint_as_float(f2tf(lky(acc[nt*4+2] + bb0)));
        sm[OF_Z + (mrow + 8 + lq) * ZST + n0 + 1] = __uint_as_float(f2tf(lky(acc[nt*4+3] + bb1)));
    }
    __syncthreads();

    // GEMM2: out = Y @ Wf^T + bf   (N=16, K=256)
    float acc2[8];
#pragma unroll
    for (int q = 0; q < 8; q++) acc2[q] = 0.f;
    const unsigned* fp = (const unsigned*)&sm[OF_WF + lq * ZST + lr];
    for (int k0 = 0; k0 < 256; k0 += 8) {
        unsigned a0 = zp0[k0], a1 = zp1[k0], a2 = zp0[k0 + 4], a3 = zp1[k0 + 4];
#pragma unroll
        for (int nt = 0; nt < 2; nt++) {
            unsigned bb0 = fp[nt * 8 * ZST + k0];
            unsigned bb1 = fp[nt * 8 * ZST + k0 + 4];
            MMA_TF32(&acc2[nt * 4], a0, a1, a2, a3, bb0, bb1);
        }
    }
#pragma unroll
    for (int nt = 0; nt < 2; nt++) {
        int n0 = nt * 8 + 2 * lr;
        float bf0 = __ldg(&bf[n0]), bf1 = __ldg(&bf[n0 + 1]);
        int p = mrow + lq;
        int g0 = ((i0 + (p >> 6)) * NSEQ + j0 + (p & 63)) * 16;
        out[g0 + n0]     = acc2[nt * 4 + 0] + bf0;
        out[g0 + n0 + 1] = acc2[nt * 4 + 1] + bf1;
        int p2 = p + 8;
        int g1 = ((i0 + (p2 >> 6)) * NSEQ + j0 + (p2 & 63)) * 16;
        out[g1 + n0]     = acc2[nt * 4 + 2] + bf0;
        out[g1 + n0 + 1] = acc2[nt * 4 + 3] + bf1;
    }
}

// ---------------- launch ------------------------------------------------------
extern "C" void kernel_launch(void* const* d_in, const int* in_sizes, int n_in,
                              void* d_out, int out_size) {
    const int*   wid   = (const int*)d_in[0];
    const int*   tyid  = (const int*)d_in[1];
    const float* etab  = (const float*)d_in[2];
    const float* ttab  = (const float*)d_in[3];
    const float* Wih_f = (const float*)d_in[4];
    const float* Whh_f = (const float*)d_in[5];
    const float* bih_f = (const float*)d_in[6];
    const float* bhh_f = (const float*)d_in[7];
    const float* Wih_b = (const float*)d_in[8];
    const float* Whh_b = (const float*)d_in[9];
    const float* bih_b = (const float*)d_in[10];
    const float* bhh_b = (const float*)d_in[11];
    const float* W1    = (const float*)d_in[12];
    const float* b1    = (const float*)d_in[13];
    const float* W2    = (const float*)d_in[14];
    const float* b2    = (const float*)d_in[15];
    const float* Wf    = (const float*)d_in[16];
    const float* bf    = (const float*)d_in[17];
    float* out = (float*)d_out;

    cudaFuncSetAttribute(pair3_kernel,
                         cudaFuncAttributeMaxDynamicSharedMemorySize, P3_TOT);

    embed_kernel<<<NSEQ, 352>>>(wid, tyid, etab, ttab);
    gx_kernel<<<dim3(128, 2), 384>>>(Wih_f, bih_f, bhh_f, Wih_b, bih_b, bhh_b);
    lstm_kernel<<<16, 256>>>(Whh_f, Whh_b);
    ab_kernel<<<64, 384>>>(W1);
    pair3_kernel<<<dim3(6, 192), 256, P3_TOT>>>(b1, b2, W2, Wf, bf, out);
}

// round 12
// speedup vs baseline: 2.0510x; 1.0725x over previous
#include <cuda_runtime.h>
#include <cooperative_groups.h>

namespace cg = cooperative_groups;

#define NSEQ 384
#define IND  350
#define G4   1024

// ---------------- scratch (device globals) -----------------------------------
__device__ float g_xT[IND * NSEQ];          // x transposed [350][384]
__device__ float g_gx[2][NSEQ][G4];         // gate preactivations (incl. biases)
__device__ float g_HT[512 * NSEQ];          // h transposed [512][384]
__device__ float g_AB[NSEQ * 512];          // [384][A(256) | B(256)]

// ---------------- 1) embedding gather -> xT ----------------------------------
__global__ __launch_bounds__(352) void embed_kernel(
    const int* __restrict__ wid, const int* __restrict__ tyid,
    const float* __restrict__ etab, const float* __restrict__ ttab)
{
    int t = blockIdx.x, d = threadIdx.x;
    if (d < IND) {
        float v = (d < 300) ? etab[wid[t] * 300 + d]
                            : ttab[tyid[t] * 50 + (d - 300)];
        g_xT[d * NSEQ + t] = v;
    }
}

// ---------------- 2) gx = x @ Wih^T + bih + bhh (both dirs) -------------------
__global__ __launch_bounds__(384) void gx_kernel(
    const float* __restrict__ Wih_f, const float* __restrict__ bih_f, const float* __restrict__ bhh_f,
    const float* __restrict__ Wih_b, const float* __restrict__ bih_b, const float* __restrict__ bhh_b)
{
    int dir = blockIdx.y;
    const float* Wih = dir ? Wih_b : Wih_f;
    const float* bi  = dir ? bih_b : bih_f;
    const float* bh  = dir ? bhh_b : bhh_f;
    int t = threadIdx.x;
    int G0 = blockIdx.x * 8;
    const float* wp[8];
#pragma unroll
    for (int g = 0; g < 8; g++) wp[g] = Wih + (G0 + g) * IND;
    float acc[8] = {0.f,0.f,0.f,0.f,0.f,0.f,0.f,0.f};
    for (int k = 0; k < IND; k++) {
        float xv = g_xT[k * NSEQ + t];
#pragma unroll
        for (int g = 0; g < 8; g++) acc[g] = fmaf(xv, wp[g][k], acc[g]);
    }
#pragma unroll
    for (int g = 0; g < 8; g++)
        g_gx[dir][t][G0 + g] = acc[g] + bi[G0 + g] + bh[G0 + g];
}

// ---------------- fast activations -------------------------------------------
__device__ __forceinline__ float fast_sigmoid(float x) {
    return 1.f / (1.f + __expf(-x));
}
__device__ __forceinline__ float fast_tanh(float x) {
    return 1.f - 2.f / (__expf(2.f * x) + 1.f);
}

__device__ __forceinline__ void cluster_arrive_rel() {
    asm volatile("barrier.cluster.arrive.aligned;" ::: "memory");
}
__device__ __forceinline__ void cluster_wait_acq() {
    asm volatile("barrier.cluster.wait.aligned;" ::: "memory");
}

// ---------------- 4) BiLSTM: 2 clusters x 8 CTAs, Whh in registers -----------
// R7 skeleton with SPLIT cluster arrive/wait: arrive (release) at step end
// after all hb[cur] reads + writer DSMEM stores; wait at top of next step
// AFTER the gx prefetch LDG has been issued, so the barrier wait overlaps
// the global-memory latency instead of exposing it at gather time.
__global__ void __cluster_dims__(8, 1, 1) __launch_bounds__(256, 1)
lstm_kernel(const float* __restrict__ Whh_f, const float* __restrict__ Whh_b)
{
    __shared__ __align__(16) float hb[2][256];
    __shared__ __align__(16) float psum[256];

    cg::cluster_group cluster = cg::this_cluster();
    int rk  = (int)cluster.block_rank();
    int dir = blockIdx.x >> 3;
    const float* Whh = dir ? Whh_b : Whh_f;
    int tid  = threadIdx.x;
    int l    = tid & 127;
    int half = tid >> 7;
    int G    = ((l >> 5) << 8) + (rk << 5) + (l & 31);

    unsigned long long w2r[64];
    const float* wsrc = Whh + G * 256 + half * 128;
#pragma unroll
    for (int q = 0; q < 32; q++) {
        float4 v = *(const float4*)&wsrc[q * 4];
        asm("mov.b64 %0, {%1, %2};" : "=l"(w2r[2 * q])     : "f"(v.x), "f"(v.y));
        asm("mov.b64 %0, {%1, %2};" : "=l"(w2r[2 * q + 1]) : "f"(v.z), "f"(v.w));
    }
    hb[0][tid] = 0.f;
    float c = 0.f;

    float* dsth[8];
    if (tid < 32) {
#pragma unroll
        for (int pr = 0; pr < 8; pr++)
            dsth[pr] = cluster.map_shared_rank(&hb[0][0], pr);
    }
    __syncthreads();
    cluster.sync();          // hb[0] zeroed + visible cluster-wide

    const float* gx = &g_gx[dir][0][0];

    for (int t = 0; t < NSEQ; t++) {
        int cur = t & 1, nxt = cur ^ 1;
        int idx = dir ? (NSEQ - 1 - t) : t;

        float gxv0 = 0.f, gxv1 = 0.f, gxv2 = 0.f, gxv3 = 0.f;
        if (tid < 32) {  // prefetch issued BEFORE the barrier wait
            const float* gp = gx + idx * G4 + (rk << 5) + tid;
            gxv0 = gp[0]; gxv1 = gp[256]; gxv2 = gp[512]; gxv3 = gp[768];
        }

        if (t > 0) cluster_wait_acq();   // h(t-1) now visible in hb[cur]

        const ulonglong2* h2 = (const ulonglong2*)&hb[cur][half * 128];
        unsigned long long a0 = 0ull, a1 = 0ull, a2 = 0ull, a3 = 0ull;
#pragma unroll
        for (int q = 0; q < 32; q += 2) {
            ulonglong2 hv0 = h2[q];
            ulonglong2 hv1 = h2[q + 1];
            asm("fma.rn.f32x2 %0, %1, %2, %0;" : "+l"(a0) : "l"(w2r[2*q]),   "l"(hv0.x));
            asm("fma.rn.f32x2 %0, %1, %2, %0;" : "+l"(a1) : "l"(w2r[2*q+1]), "l"(hv0.y));
            asm("fma.rn.f32x2 %0, %1, %2, %0;" : "+l"(a2) : "l"(w2r[2*q+2]), "l"(hv1.x));
            asm("fma.rn.f32x2 %0, %1, %2, %0;" : "+l"(a3) : "l"(w2r[2*q+3]), "l"(hv1.y));
        }
        float s0, s1, s2, s3, s4, s5, s6, s7;
        asm("mov.b64 {%0, %1}, %2;" : "=f"(s0), "=f"(s1) : "l"(a0));
        asm("mov.b64 {%0, %1}, %2;" : "=f"(s2), "=f"(s3) : "l"(a1));
        asm("mov.b64 {%0, %1}, %2;" : "=f"(s4), "=f"(s5) : "l"(a2));
        asm("mov.b64 {%0, %1}, %2;" : "=f"(s6), "=f"(s7) : "l"(a3));
        psum[tid] = ((s0 + s1) + (s2 + s3)) + ((s4 + s5) + (s6 + s7));
        __syncthreads();

        if (tid < 32) {
            float ai = psum[tid]       + psum[128 + tid] + gxv0;
            float af = psum[32 + tid]  + psum[160 + tid] + gxv1;
            float ag = psum[64 + tid]  + psum[192 + tid] + gxv2;
            float ao = psum[96 + tid]  + psum[224 + tid] + gxv3;
            float iv = fast_sigmoid(ai);
            float fv = fast_sigmoid(af);
            float gv = fast_tanh(ag);
            float ov = fast_sigmoid(ao);
            c = fv * c + iv * gv;
            float hn = ov * fast_tanh(c);
            int col = (rk << 5) + tid;
            if (t < NSEQ - 1) {
                int off = (nxt << 8) + col;
#pragma unroll
                for (int pr = 0; pr < 8; pr++) dsth[pr][off] = hn;
            }
            g_HT[(dir * 256 + col) * NSEQ + idx] = hn;
        }
        if (t < NSEQ - 1) cluster_arrive_rel();  // release writer stores
    }
    cluster.sync();   // no CTA exits while peers may still touch its smem
}

// ---------------- 5) A|B = h @ [W1a|W1b]^T ------------------------------------
// Re-grid: 384 small CTAs (128 thr) so every SM has multiple blocks in flight.
__global__ __launch_bounds__(128) void ab_kernel(const float* __restrict__ W1)
{
    int t  = blockIdx.y * 128 + threadIdx.x;
    int f0 = blockIdx.x * 4;
    const float* wp[4];
#pragma unroll
    for (int g = 0; g < 4; g++) {
        int f = f0 + g;
        wp[g] = (f < 256) ? (W1 + f * 1024) : (W1 + (f - 256) * 1024 + 512);
    }
    float acc[4] = {0.f, 0.f, 0.f, 0.f};
#pragma unroll 4
    for (int k = 0; k < 512; k++) {
        float hv = g_HT[k * NSEQ + t];
#pragma unroll
        for (int g = 0; g < 4; g++) acc[g] = fmaf(hv, wp[g][k], acc[g]);
    }
#pragma unroll
    for (int g = 0; g < 4; g++) g_AB[t * 512 + f0 + g] = acc[g];
}

// ---------------- 6) pair MLP via mma.sync tf32 (IDENTICAL to passing R11) ----
#define ZST   260
#define OF_Z  0                         // Z / Y  [128][260]
#define OF_W2 (128 * ZST)               // W2 chunk [32][260]
#define OF_WF (OF_W2 + 32 * ZST)        // Wf [16][260]
#define OF_A  (OF_WF + 16 * ZST)        // A_i + b1 [2][256]
#define OF_B2 (OF_A + 512)              // b2 [256]
#define P3_TOT ((OF_B2 + 256) * 4)      // 186112 bytes

__device__ __forceinline__ unsigned f2tf(float f) {
    unsigned r;
    asm("cvt.rna.tf32.f32 %0, %1;" : "=r"(r) : "f"(f));
    return r;
}
__device__ __forceinline__ float lky(float v) { return fmaxf(v, 0.01f * v); }

#define MMA_TF32(d, a0, a1, a2, a3, b0, b1)                                     \
    asm volatile("mma.sync.aligned.m16n8k8.row.col.f32.tf32.tf32.f32 "          \
                 "{%0,%1,%2,%3}, {%4,%5,%6,%7}, {%8,%9}, {%0,%1,%2,%3};"        \
                 : "+f"((d)[0]), "+f"((d)[1]), "+f"((d)[2]), "+f"((d)[3])       \
                 : "r"(a0), "r"(a1), "r"(a2), "r"(a3), "r"(b0), "r"(b1))

__global__ __launch_bounds__(256, 1) void pair3_kernel(
    const float* __restrict__ b1, const float* __restrict__ b2,
    const float* __restrict__ W2, const float* __restrict__ Wf,
    const float* __restrict__ bf, float* __restrict__ out)
{
    extern __shared__ __align__(16) float sm[];
    int tid = threadIdx.x, wid = tid >> 5, lane = tid & 31;
    int i0 = blockIdx.y * 2, j0 = blockIdx.x * 64;
    int lq = lane >> 2, lr = lane & 3;        // quad row / col within frag

    // stage A rows (+b1), b2, Wf
    sm[OF_A + tid]       = g_AB[(i0 + 0) * 512 + tid] + b1[tid];
    sm[OF_A + 256 + tid] = g_AB[(i0 + 1) * 512 + tid] + b1[tid];
    sm[OF_B2 + tid] = b2[tid];
#pragma unroll
    for (int it = 0; it < 16; it++) {
        int idx = tid + it * 256;             // 4096 = 16 rows x 256 k
        int r = idx >> 8, k = idx & 255;
        sm[OF_WF + r * ZST + k] = __uint_as_float(f2tf(Wf[r * 256 + k]));
    }
    __syncthreads();

    // build Z = tf32(leaky(A_ii + B_jj + b1))  [128][256]
#pragma unroll
    for (int it = 0; it < 32; it++) {
        int lin = tid + it * 256;             // 8192 float4
        int p = lin >> 6, k4 = (lin & 63) << 2;
        int ii = p >> 6, jj = p & 63;
        float4 bv = *(const float4*)&g_AB[(j0 + jj) * 512 + 256 + k4];
        const float4 av = *(const float4*)&sm[OF_A + ii * 256 + k4];
        float4 z;
        z.x = __uint_as_float(f2tf(lky(av.x + bv.x)));
        z.y = __uint_as_float(f2tf(lky(av.y + bv.y)));
        z.z = __uint_as_float(f2tf(lky(av.z + bv.z)));
        z.w = __uint_as_float(f2tf(lky(av.w + bv.w)));
        *(float4*)&sm[OF_Z + p * ZST + k4] = z;
    }

    int mrow = wid * 16;
    float acc[128];                            // [ntile 32][4]
#pragma unroll
    for (int q = 0; q < 128; q++) acc[q] = 0.f;

    const unsigned* zp0 = (const unsigned*)&sm[OF_Z + (mrow + lq) * ZST + lr];
    const unsigned* zp1 = (const unsigned*)&sm[OF_Z + (mrow + 8 + lq) * ZST + lr];

#pragma unroll
    for (int nc = 0; nc < 8; nc++) {
        // load W2 chunk rows [nc*32, nc*32+32), tf32
#pragma unroll
        for (int it = 0; it < 8; it++) {
            int lin = tid + it * 256;          // 2048 float4
            int row = lin >> 6, k4 = (lin & 63) << 2;
            float4 v = *(const float4*)&W2[(nc * 32 + row) * 256 + k4];
            float4 w;
            w.x = __uint_as_float(f2tf(v.x)); w.y = __uint_as_float(f2tf(v.y));
            w.z = __uint_as_float(f2tf(v.z)); w.w = __uint_as_float(f2tf(v.w));
            *(float4*)&sm[OF_W2 + row * ZST + k4] = w;
        }
        __syncthreads();

        const unsigned* wp = (const unsigned*)&sm[OF_W2 + lq * ZST + lr];
        for (int k0 = 0; k0 < 256; k0 += 8) {
            unsigned a0 = zp0[k0], a1 = zp1[k0], a2 = zp0[k0 + 4], a3 = zp1[k0 + 4];
#pragma unroll
            for (int nt = 0; nt < 4; nt++) {
                unsigned bb0 = wp[nt * 8 * ZST + k0];
                unsigned bb1 = wp[nt * 8 * ZST + k0 + 4];
                MMA_TF32(&acc[(nc * 4 + nt) * 4], a0, a1, a2, a3, bb0, bb1);
            }
        }
        __syncthreads();
    }

    // epilogue: Y = tf32(leaky(D + b2)) over Z buffer
#pragma unroll
    for (int nt = 0; nt < 32; nt++) {
        int n0 = nt * 8 + 2 * lr;
        float bb0 = sm[OF_B2 + n0], bb1 = sm[OF_B2 + n0 + 1];
        sm[OF_Z + (mrow + lq) * ZST + n0]         = __uint_as_float(f2tf(lky(acc[nt*4+0] + bb0)));
        sm[OF_Z + (mrow + lq) * ZST + n0 + 1]     = __uint_as_float(f2tf(lky(acc[nt*4+1] + bb1)));
        sm[OF_Z + (mrow + 8 + lq) * ZST + n0]     = __uint_as_float(f2tf(lky(acc[nt*4+2] + bb0)));
        sm[OF_Z + (mrow + 8 + lq) * ZST + n0 + 1] = __uint_as_float(f2tf(lky(acc[nt*4+3] + bb1)));
    }
    __syncthreads();

    // GEMM2: out = Y @ Wf^T + bf   (N=16, K=256)
    float acc2[8];
#pragma unroll
    for (int q = 0; q < 8; q++) acc2[q] = 0.f;
    const unsigned* fp = (const unsigned*)&sm[OF_WF + lq * ZST + lr];
    for (int k0 = 0; k0 < 256; k0 += 8) {
        unsigned a0 = zp0[k0], a1 = zp1[k0], a2 = zp0[k0 + 4], a3 = zp1[k0 + 4];
#pragma unroll
        for (int nt = 0; nt < 2; nt++) {
            unsigned bb0 = fp[nt * 8 * ZST + k0];
            unsigned bb1 = fp[nt * 8 * ZST + k0 + 4];
            MMA_TF32(&acc2[nt * 4], a0, a1, a2, a3, bb0, bb1);
        }
    }
#pragma unroll
    for (int nt = 0; nt < 2; nt++) {
        int n0 = nt * 8 + 2 * lr;
        float bf0 = __ldg(&bf[n0]), bf1 = __ldg(&bf[n0 + 1]);
        int p = mrow + lq;
        int g0 = ((i0 + (p >> 6)) * NSEQ + j0 + (p & 63)) * 16;
        out[g0 + n0]     = acc2[nt * 4 + 0] + bf0;
        out[g0 + n0 + 1] = acc2[nt * 4 + 1] + bf1;
        int p2 = p + 8;
        int g1 = ((i0 + (p2 >> 6)) * NSEQ + j0 + (p2 & 63)) * 16;
        out[g1 + n0]     = acc2[nt * 4 + 2] + bf0;
        out[g1 + n0 + 1] = acc2[nt * 4 + 3] + bf1;
    }
}

// ---------------- launch ------------------------------------------------------
extern "C" void kernel_launch(void* const* d_in, const int* in_sizes, int n_in,
                              void* d_out, int out_size) {
    const int*   wid   = (const int*)d_in[0];
    const int*   tyid  = (const int*)d_in[1];
    const float* etab  = (const float*)d_in[2];
    const float* ttab  = (const float*)d_in[3];
    const float* Wih_f = (const float*)d_in[4];
    const float* Whh_f = (const float*)d_in[5];
    const float* bih_f = (const float*)d_in[6];
    const float* bhh_f = (const float*)d_in[7];
    const float* Wih_b = (const float*)d_in[8];
    const float* Whh_b = (const float*)d_in[9];
    const float* bih_b = (const float*)d_in[10];
    const float* bhh_b = (const float*)d_in[11];
    const float* W1    = (const float*)d_in[12];
    const float* b1    = (const float*)d_in[13];
    const float* W2    = (const float*)d_in[14];
    const float* b2    = (const float*)d_in[15];
    const float* Wf    = (const float*)d_in[16];
    const float* bf    = (const float*)d_in[17];
    float* out = (float*)d_out;

    cudaFuncSetAttribute(pair3_kernel,
                         cudaFuncAttributeMaxDynamicSharedMemorySize, P3_TOT);

    embed_kernel<<<NSEQ, 352>>>(wid, tyid, etab, ttab);
    gx_kernel<<<dim3(128, 2), 384>>>(Wih_f, bih_f, bhh_f, Wih_b, bih_b, bhh_b);
    lstm_kernel<<<16, 256>>>(Whh_f, Whh_b);
    ab_kernel<<<dim3(128, 3), 128>>>(W1);
    pair3_kernel<<<dim3(6, 192), 256, P3_TOT>>>(b1, b2, W2, Wf, bf, out);
}

// round 14
// speedup vs baseline: 2.1649x; 1.0555x over previous
#include <cuda_runtime.h>
#include <cooperative_groups.h>

namespace cg = cooperative_groups;

#define NSEQ 384
#define IND  350
#define G4   1024

// ---------------- scratch (device globals) -----------------------------------
__device__ float g_xT[IND * NSEQ];          // x transposed [350][384]
__device__ float g_gx[2][NSEQ][G4];         // gate preactivations (incl. biases)
__device__ float g_HT[512 * NSEQ];          // h transposed [512][384]
__device__ float g_ABp[2][NSEQ * 512];      // k-split partials of [384][A|B]

// ---------------- 1) embedding gather -> xT ----------------------------------
__global__ __launch_bounds__(352) void embed_kernel(
    const int* __restrict__ wid, const int* __restrict__ tyid,
    const float* __restrict__ etab, const float* __restrict__ ttab)
{
    int t = blockIdx.x, d = threadIdx.x;
    if (d < IND) {
        float v = (d < 300) ? etab[wid[t] * 300 + d]
                            : ttab[tyid[t] * 50 + (d - 300)];
        g_xT[d * NSEQ + t] = v;
    }
}

// ---------------- 2) gx = x @ Wih^T + bih + bhh (both dirs) -------------------
__global__ __launch_bounds__(384) void gx_kernel(
    const float* __restrict__ Wih_f, const float* __restrict__ bih_f, const float* __restrict__ bhh_f,
    const float* __restrict__ Wih_b, const float* __restrict__ bih_b, const float* __restrict__ bhh_b)
{
    int dir = blockIdx.y;
    const float* Wih = dir ? Wih_b : Wih_f;
    const float* bi  = dir ? bih_b : bih_f;
    const float* bh  = dir ? bhh_b : bhh_f;
    int t = threadIdx.x;
    int G0 = blockIdx.x * 8;
    const float* wp[8];
#pragma unroll
    for (int g = 0; g < 8; g++) wp[g] = Wih + (G0 + g) * IND;
    float acc[8] = {0.f,0.f,0.f,0.f,0.f,0.f,0.f,0.f};
    for (int k = 0; k < IND; k++) {
        float xv = g_xT[k * NSEQ + t];
#pragma unroll
        for (int g = 0; g < 8; g++) acc[g] = fmaf(xv, wp[g][k], acc[g]);
    }
#pragma unroll
    for (int g = 0; g < 8; g++)
        g_gx[dir][t][G0 + g] = acc[g] + bi[G0 + g] + bh[G0 + g];
}

// ---------------- fast activations -------------------------------------------
__device__ __forceinline__ float fast_sigmoid(float x) {
    return 1.f / (1.f + __expf(-x));
}
__device__ __forceinline__ float fast_tanh(float x) {
    return 1.f - 2.f / (__expf(2.f * x) + 1.f);
}

__device__ __forceinline__ void cluster_arrive_rel() {
    asm volatile("barrier.cluster.arrive.aligned;" ::: "memory");
}
__device__ __forceinline__ void cluster_wait_acq() {
    asm volatile("barrier.cluster.wait.aligned;" ::: "memory");
}

// ---------------- 4) BiLSTM (IDENTICAL to passing R12) ------------------------
__global__ void __cluster_dims__(8, 1, 1) __launch_bounds__(256, 1)
lstm_kernel(const float* __restrict__ Whh_f, const float* __restrict__ Whh_b)
{
    __shared__ __align__(16) float hb[2][256];
    __shared__ __align__(16) float psum[256];

    cg::cluster_group cluster = cg::this_cluster();
    int rk  = (int)cluster.block_rank();
    int dir = blockIdx.x >> 3;
    const float* Whh = dir ? Whh_b : Whh_f;
    int tid  = threadIdx.x;
    int l    = tid & 127;
    int half = tid >> 7;
    int G    = ((l >> 5) << 8) + (rk << 5) + (l & 31);

    unsigned long long w2r[64];
    const float* wsrc = Whh + G * 256 + half * 128;
#pragma unroll
    for (int q = 0; q < 32; q++) {
        float4 v = *(const float4*)&wsrc[q * 4];
        asm("mov.b64 %0, {%1, %2};" : "=l"(w2r[2 * q])     : "f"(v.x), "f"(v.y));
        asm("mov.b64 %0, {%1, %2};" : "=l"(w2r[2 * q + 1]) : "f"(v.z), "f"(v.w));
    }
    hb[0][tid] = 0.f;
    float c = 0.f;

    float* dsth[8];
    if (tid < 32) {
#pragma unroll
        for (int pr = 0; pr < 8; pr++)
            dsth[pr] = cluster.map_shared_rank(&hb[0][0], pr);
    }
    __syncthreads();
    cluster.sync();          // hb[0] zeroed + visible cluster-wide

    const float* gx = &g_gx[dir][0][0];

    for (int t = 0; t < NSEQ; t++) {
        int cur = t & 1, nxt = cur ^ 1;
        int idx = dir ? (NSEQ - 1 - t) : t;

        float gxv0 = 0.f, gxv1 = 0.f, gxv2 = 0.f, gxv3 = 0.f;
        if (tid < 32) {  // prefetch issued BEFORE the barrier wait
            const float* gp = gx + idx * G4 + (rk << 5) + tid;
            gxv0 = gp[0]; gxv1 = gp[256]; gxv2 = gp[512]; gxv3 = gp[768];
        }

        if (t > 0) cluster_wait_acq();   // h(t-1) now visible in hb[cur]

        const ulonglong2* h2 = (const ulonglong2*)&hb[cur][half * 128];
        unsigned long long a0 = 0ull, a1 = 0ull, a2 = 0ull, a3 = 0ull;
#pragma unroll
        for (int q = 0; q < 32; q += 2) {
            ulonglong2 hv0 = h2[q];
            ulonglong2 hv1 = h2[q + 1];
            asm("fma.rn.f32x2 %0, %1, %2, %0;" : "+l"(a0) : "l"(w2r[2*q]),   "l"(hv0.x));
            asm("fma.rn.f32x2 %0, %1, %2, %0;" : "+l"(a1) : "l"(w2r[2*q+1]), "l"(hv0.y));
            asm("fma.rn.f32x2 %0, %1, %2, %0;" : "+l"(a2) : "l"(w2r[2*q+2]), "l"(hv1.x));
            asm("fma.rn.f32x2 %0, %1, %2, %0;" : "+l"(a3) : "l"(w2r[2*q+3]), "l"(hv1.y));
        }
        float s0, s1, s2, s3, s4, s5, s6, s7;
        asm("mov.b64 {%0, %1}, %2;" : "=f"(s0), "=f"(s1) : "l"(a0));
        asm("mov.b64 {%0, %1}, %2;" : "=f"(s2), "=f"(s3) : "l"(a1));
        asm("mov.b64 {%0, %1}, %2;" : "=f"(s4), "=f"(s5) : "l"(a2));
        asm("mov.b64 {%0, %1}, %2;" : "=f"(s6), "=f"(s7) : "l"(a3));
        psum[tid] = ((s0 + s1) + (s2 + s3)) + ((s4 + s5) + (s6 + s7));
        __syncthreads();

        if (tid < 32) {
            float ai = psum[tid]       + psum[128 + tid] + gxv0;
            float af = psum[32 + tid]  + psum[160 + tid] + gxv1;
            float ag = psum[64 + tid]  + psum[192 + tid] + gxv2;
            float ao = psum[96 + tid]  + psum[224 + tid] + gxv3;
            float iv = fast_sigmoid(ai);
            float fv = fast_sigmoid(af);
            float gv = fast_tanh(ag);
            float ov = fast_sigmoid(ao);
            c = fv * c + iv * gv;
            float hn = ov * fast_tanh(c);
            int col = (rk << 5) + tid;
            if (t < NSEQ - 1) {
                int off = (nxt << 8) + col;
#pragma unroll
                for (int pr = 0; pr < 8; pr++) dsth[pr][off] = hn;
            }
            g_HT[(dir * 256 + col) * NSEQ + idx] = hn;
        }
        if (t < NSEQ - 1) cluster_arrive_rel();  // release writer stores
    }
    cluster.sync();   // no CTA exits while peers may still touch its smem
}

// ---------------- 5) A|B partials = h @ [W1a|W1b]^T (k-split x2) --------------
// grid (256, 3, 2): 1536 CTAs. Each thread: 2 f-outputs over a 256-k half.
__global__ __launch_bounds__(128) void ab_kernel(const float* __restrict__ W1)
{
    int t  = blockIdx.y * 128 + threadIdx.x;
    int f0 = blockIdx.x * 2;
    int kz = blockIdx.z;
    const float* wp[2];
#pragma unroll
    for (int g = 0; g < 2; g++) {
        int f = f0 + g;
        wp[g] = ((f < 256) ? (W1 + f * 1024) : (W1 + (f - 256) * 1024 + 512))
                + kz * 256;
    }
    const float* hp = &g_HT[(kz * 256) * NSEQ + t];
    float acc0 = 0.f, acc1 = 0.f;
#pragma unroll 8
    for (int k = 0; k < 256; k++) {
        float hv = hp[k * NSEQ];
        acc0 = fmaf(hv, wp[0][k], acc0);
        acc1 = fmaf(hv, wp[1][k], acc1);
    }
    g_ABp[kz][t * 512 + f0]     = acc0;
    g_ABp[kz][t * 512 + f0 + 1] = acc1;
}

// ---------------- 6) pair MLP via mma.sync tf32 (R11 pass + partial sums) -----
#define ZST   260
#define OF_Z  0                         // Z / Y  [128][260]
#define OF_W2 (128 * ZST)               // W2 chunk [32][260]
#define OF_WF (OF_W2 + 32 * ZST)        // Wf [16][260]
#define OF_A  (OF_WF + 16 * ZST)        // A_i + b1 [2][256]
#define OF_B2 (OF_A + 512)              // b2 [256]
#define P3_TOT ((OF_B2 + 256) * 4)      // 186112 bytes

__device__ __forceinline__ unsigned f2tf(float f) {
    unsigned r;
    asm("cvt.rna.tf32.f32 %0, %1;" : "=r"(r) : "f"(f));
    return r;
}
__device__ __forceinline__ float lky(float v) { return fmaxf(v, 0.01f * v); }

#define MMA_TF32(d, a0, a1, a2, a3, b0, b1)                                     \
    asm volatile("mma.sync.aligned.m16n8k8.row.col.f32.tf32.tf32.f32 "          \
                 "{%0,%1,%2,%3}, {%4,%5,%6,%7}, {%8,%9}, {%0,%1,%2,%3};"        \
                 : "+f"((d)[0]), "+f"((d)[1]), "+f"((d)[2]), "+f"((d)[3])       \
                 : "r"(a0), "r"(a1), "r"(a2), "r"(a3), "r"(b0), "r"(b1))

__global__ __launch_bounds__(256, 1) void pair3_kernel(
    const float* __restrict__ b1, const float* __restrict__ b2,
    const float* __restrict__ W2, const float* __restrict__ Wf,
    const float* __restrict__ bf, float* __restrict__ out)
{
    extern __shared__ __align__(16) float sm[];
    int tid = threadIdx.x, wid = tid >> 5, lane = tid & 31;
    int i0 = blockIdx.y * 2, j0 = blockIdx.x * 64;
    int lq = lane >> 2, lr = lane & 3;        // quad row / col within frag

    // stage A rows (+b1) from partials, b2, Wf
    sm[OF_A + tid]       = g_ABp[0][(i0 + 0) * 512 + tid]
                         + g_ABp[1][(i0 + 0) * 512 + tid] + b1[tid];
    sm[OF_A + 256 + tid] = g_ABp[0][(i0 + 1) * 512 + tid]
                         + g_ABp[1][(i0 + 1) * 512 + tid] + b1[tid];
    sm[OF_B2 + tid] = b2[tid];
#pragma unroll
    for (int it = 0; it < 16; it++) {
        int idx = tid + it * 256;             // 4096 = 16 rows x 256 k
        int r = idx >> 8, k = idx & 255;
        sm[OF_WF + r * ZST + k] = __uint_as_float(f2tf(Wf[r * 256 + k]));
    }
    __syncthreads();

    // build Z = tf32(leaky(A_ii + B_jj + b1))  [128][256]
#pragma unroll
    for (int it = 0; it < 32; it++) {
        int lin = tid + it * 256;             // 8192 float4
        int p = lin >> 6, k4 = (lin & 63) << 2;
        int ii = p >> 6, jj = p & 63;
        float4 bv0 = *(const float4*)&g_ABp[0][(j0 + jj) * 512 + 256 + k4];
        float4 bv1 = *(const float4*)&g_ABp[1][(j0 + jj) * 512 + 256 + k4];
        const float4 av = *(const float4*)&sm[OF_A + ii * 256 + k4];
        float4 z;
        z.x = __uint_as_float(f2tf(lky(av.x + bv0.x + bv1.x)));
        z.y = __uint_as_float(f2tf(lky(av.y + bv0.y + bv1.y)));
        z.z = __uint_as_float(f2tf(lky(av.z + bv0.z + bv1.z)));
        z.w = __uint_as_float(f2tf(lky(av.w + bv0.w + bv1.w)));
        *(float4*)&sm[OF_Z + p * ZST + k4] = z;
    }

    int mrow = wid * 16;
    float acc[128];                            // [ntile 32][4]
#pragma unroll
    for (int q = 0; q < 128; q++) acc[q] = 0.f;

    const unsigned* zp0 = (const unsigned*)&sm[OF_Z + (mrow + lq) * ZST + lr];
    const unsigned* zp1 = (const unsigned*)&sm[OF_Z + (mrow + 8 + lq) * ZST + lr];

#pragma unroll
    for (int nc = 0; nc < 8; nc++) {
        // load W2 chunk rows [nc*32, nc*32+32), tf32
#pragma unroll
        for (int it = 0; it < 8; it++) {
            int lin = tid + it * 256;          // 2048 float4
            int row = lin >> 6, k4 = (lin & 63) << 2;
            float4 v = *(const float4*)&W2[(nc * 32 + row) * 256 + k4];
            float4 w;
            w.x = __uint_as_float(f2tf(v.x)); w.y = __uint_as_float(f2tf(v.y));
            w.z = __uint_as_float(f2tf(v.z)); w.w = __uint_as_float(f2tf(v.w));
            *(float4*)&sm[OF_W2 + row * ZST + k4] = w;
        }
        __syncthreads();

        const unsigned* wp = (const unsigned*)&sm[OF_W2 + lq * ZST + lr];
        for (int k0 = 0; k0 < 256; k0 += 8) {
            unsigned a0 = zp0[k0], a1 = zp1[k0], a2 = zp0[k0 + 4], a3 = zp1[k0 + 4];
#pragma unroll
            for (int nt = 0; nt < 4; nt++) {
                unsigned bb0 = wp[nt * 8 * ZST + k0];
                unsigned bb1 = wp[nt * 8 * ZST + k0 + 4];
                MMA_TF32(&acc[(nc * 4 + nt) * 4], a0, a1, a2, a3, bb0, bb1);
            }
        }
        __syncthreads();
    }

    // epilogue: Y = tf32(leaky(D + b2)) over Z buffer
#pragma unroll
    for (int nt = 0; nt < 32; nt++) {
        int n0 = nt * 8 + 2 * lr;
        float bb0 = sm[OF_B2 + n0], bb1 = sm[OF_B2 + n0 + 1];
        sm[OF_Z + (mrow + lq) * ZST + n0]         = __uint_as_float(f2tf(lky(acc[nt*4+0] + bb0)));
        sm[OF_Z + (mrow + lq) * ZST + n0 + 1]     = __uint_as_float(f2tf(lky(acc[nt*4+1] + bb1)));
        sm[OF_Z + (mrow + 8 + lq) * ZST + n0]     = __uint_as_float(f2tf(lky(acc[nt*4+2] + bb0)));
        sm[OF_Z + (mrow + 8 + lq) * ZST + n0 + 1] = __uint_as_float(f2tf(lky(acc[nt*4+3] + bb1)));
    }
    __syncthreads();

    // GEMM2: out = Y @ Wf^T + bf   (N=16, K=256)
    float acc2[8];
#pragma unroll
    for (int q = 0; q < 8; q++) acc2[q] = 0.f;
    const unsigned* fp = (const unsigned*)&sm[OF_WF + lq * ZST + lr];
    for (int k0 = 0; k0 < 256; k0 += 8) {
        unsigned a0 = zp0[k0], a1 = zp1[k0], a2 = zp0[k0 + 4], a3 = zp1[k0 + 4];
#pragma unroll
        for (int nt = 0; nt < 2; nt++) {
            unsigned bb0 = fp[nt * 8 * ZST + k0];
            unsigned bb1 = fp[nt * 8 * ZST + k0 + 4];
            MMA_TF32(&acc2[nt * 4], a0, a1, a2, a3, bb0, bb1);
        }
    }
#pragma unroll
    for (int nt = 0; nt < 2; nt++) {
        int n0 = nt * 8 + 2 * lr;
        float bf0 = __ldg(&bf[n0]), bf1 = __ldg(&bf[n0 + 1]);
        int p = mrow + lq;
        int g0 = ((i0 + (p >> 6)) * NSEQ + j0 + (p & 63)) * 16;
        out[g0 + n0]     = acc2[nt * 4 + 0] + bf0;
        out[g0 + n0 + 1] = acc2[nt * 4 + 1] + bf1;
        int p2 = p + 8;
        int g1 = ((i0 + (p2 >> 6)) * NSEQ + j0 + (p2 & 63)) * 16;
        out[g1 + n0]     = acc2[nt * 4 + 2] + bf0;
        out[g1 + n0 + 1] = acc2[nt * 4 + 3] + bf1;
    }
}

// ---------------- launch ------------------------------------------------------
extern "C" void kernel_launch(void* const* d_in, const int* in_sizes, int n_in,
                              void* d_out, int out_size) {
    const int*   wid   = (const int*)d_in[0];
    const int*   tyid  = (const int*)d_in[1];
    const float* etab  = (const float*)d_in[2];
    const float* ttab  = (const float*)d_in[3];
    const float* Wih_f = (const float*)d_in[4];
    const float* Whh_f = (const float*)d_in[5];
    const float* bih_f = (const float*)d_in[6];
    const float* bhh_f = (const float*)d_in[7];
    const float* Wih_b = (const float*)d_in[8];
    const float* Whh_b = (const float*)d_in[9];
    const float* bih_b = (const float*)d_in[10];
    const float* bhh_b = (const float*)d_in[11];
    const float* W1    = (const float*)d_in[12];
    const float* b1    = (const float*)d_in[13];
    const float* W2    = (const float*)d_in[14];
    const float* b2    = (const float*)d_in[15];
    const float* Wf    = (const float*)d_in[16];
    const float* bf    = (const float*)d_in[17];
    float* out = (float*)d_out;

    cudaFuncSetAttribute(pair3_kernel,
                         cudaFuncAttributeMaxDynamicSharedMemorySize, P3_TOT);

    embed_kernel<<<NSEQ, 352>>>(wid, tyid, etab, ttab);
    gx_kernel<<<dim3(128, 2), 384>>>(Wih_f, bih_f, bhh_f, Wih_b, bih_b, bhh_b);
    lstm_kernel<<<16, 256>>>(Whh_f, Whh_b);
    ab_kernel<<<dim3(256, 3, 2), 128>>>(W1);
    pair3_kernel<<<dim3(6, 192), 256, P3_TOT>>>(b1, b2, W2, Wf, bf, out);
}